// round 8
// baseline (speedup 1.0000x reference)
#include <cuda_runtime.h>
#include <stdint.h>

// GateLayer: x (4096,4096) f32, idx_l/idx_r (16384,) int, alpha (16384,3) f32,
// y (4096,16384) f32.
#define MDIM    4096
#define GMAX    16384
#define ROWS    4           // rows per tile (one 16-B quad per column)
#define XTILE_BYTES   (MDIM * 16)            // 65536
#define STAGE_OFF     XTILE_BYTES            // output staging after x tile
#define SWEEP_G       2048                   // g per sweep (512 thr x 4 g)
#define STAGE_ROW_B   (SWEEP_G * 4)          // 8192 B per row
#define STAGE_BYTES   (ROWS * STAGE_ROW_B)   // 32768
#define SMEM_TOTAL    (XTILE_BYTES + STAGE_BYTES)   // 98304

// Static device scratch (no cudaMalloc allowed)
__device__ __align__(16) int    g_il[GMAX];
__device__ __align__(16) int    g_ir[GMAX];
__device__ __align__(16) float2 g_cf[GMAX];

// ---------------------------------------------------------------------------
// Prep with fused int64/int32 detection. Every block samples the first 512
// 32-bit words of il/ir: OR of odd words is 0 iff idx is int64 (values < 4096
// -> high halves zero). All blocks reach the same decision independently.
// Then fold softmax(alpha) into (c_ab, c_s): y = c_ab*ab + c_s*(a+b).
// ---------------------------------------------------------------------------
__global__ void prep_kernel(const unsigned int* __restrict__ il_raw,
                            const unsigned int* __restrict__ ir_raw,
                            const float* __restrict__ alpha, int G) {
    int t = threadIdx.x;
    unsigned int acc = 0;
    int i = t * 2 + 1;
    if (i < min(G, 512)) acc = il_raw[i] | ir_raw[i];
    int is64 = !__syncthreads_or(acc != 0u);

    int g = blockIdx.x * blockDim.x + t;
    if (g >= G) return;
    int il, ir;
    if (is64) { il = (int)il_raw[2 * g]; ir = (int)ir_raw[2 * g]; }
    else      { il = (int)il_raw[g];     ir = (int)ir_raw[g];     }
    g_il[g] = il;
    g_ir[g] = ir;

    float a0 = alpha[3 * g + 0], a1 = alpha[3 * g + 1], a2 = alpha[3 * g + 2];
    float m  = fmaxf(a0, fmaxf(a1, a2));
    float e0 = expf(a0 - m), e1 = expf(a1 - m), e2 = expf(a2 - m);
    float inv = 1.0f / (e0 + e1 + e2);
    float w0 = e0 * inv, w1 = e1 * inv, w2 = e2 * inv;
    g_cf[g] = make_float2(w0 - w1 - 2.0f * w2, w1 + w2);
}

// ---------------------------------------------------------------------------
// Main kernel, 2 blocks/SM. SMEM: [0,64K) = 4 rows of x transposed (column c
// is one 16-B quad at P(c) = (c ^ ((c>>3)&7)) << 4; staging STS conflict-free,
// one LDS.128 gathers rows 0-3 of column c); [64K,96K) = output staging.
// Per sweep: compute 4 rows x 2048 g into staging (STS.128, dense), then one
// thread issues 4 x cp.async.bulk (8 KB/row) - GMEM writes bypass LSU issue.
// Per 16 outputs: 8 LDS.128 + 4 STS.128 + 4 LDG (no STG).
// ---------------------------------------------------------------------------
__global__ __launch_bounds__(512, 2)
void gate_kernel(const float* __restrict__ x, float* __restrict__ y,
                 int G, int gPerBlock) {
    extern __shared__ float sm[];
    char* smb = (char*)sm;
    uint32_t smem_u32;
    asm("{ .reg .u64 t; cvta.to.shared.u64 t, %1; cvt.u32.u64 %0, t; }"
        : "=r"(smem_u32) : "l"(smb));

    const int tid  = threadIdx.x;
    const int warp = tid >> 5, lane = tid & 31;
    const int row0   = blockIdx.x * ROWS;
    const int gstart = blockIdx.y * gPerBlock;

    // ---- Stage x: 4 rows, transposed + swizzled, conflict-free STS ----
    {
        const int r  = lane >> 3;              // 0..3
        const int cs = lane & 7;               // 0..7
        const float4* x4 = (const float4*)(x + (size_t)(row0 + r) * MDIM);
        #pragma unroll
        for (int i = 0; i < 8; i++) {
            int c4 = warp * 8 + cs + i * 128;  // float4 index 0..1023
            float4 v = x4[c4];
            int c0 = c4 * 4;
            #pragma unroll
            for (int j = 0; j < 4; j++) {
                int c = c0 + j;
                int P = ((c ^ ((c >> 3) & 7)) << 4) + r * 4;
                *(float*)(smb + P) = (&v.x)[j];
            }
        }
    }
    __syncthreads();

    float* yrow0 = y + (size_t)row0 * G;
    const int sweeps = gPerBlock / SWEEP_G;

    int gb = gstart + tid * 4;                 // tid==0 holds the sweep base
    #pragma unroll 1
    for (int s = 0; s < sweeps; s++, gb += SWEEP_G) {
        int4   il  = *(const int4*)&g_il[gb];
        int4   ir  = *(const int4*)&g_ir[gb];
        float4 cfA = *(const float4*)&g_cf[gb];       // (cab0,cs0,cab1,cs1)
        float4 cfB = *(const float4*)&g_cf[gb + 2];   // (cab2,cs2,cab3,cs3)

        int P0 = (il.x ^ ((il.x >> 3) & 7)) << 4;
        int Q0 = (ir.x ^ ((ir.x >> 3) & 7)) << 4;
        int P1 = (il.y ^ ((il.y >> 3) & 7)) << 4;
        int Q1 = (ir.y ^ ((ir.y >> 3) & 7)) << 4;
        int P2 = (il.z ^ ((il.z >> 3) & 7)) << 4;
        int Q2 = (ir.z ^ ((ir.z >> 3) & 7)) << 4;
        int P3 = (il.w ^ ((il.w >> 3) & 7)) << 4;
        int Q3 = (ir.w ^ ((ir.w >> 3) & 7)) << 4;

        float4 v0, v1, v2, v3;   // v{r} = outputs (g0,g1,g2,g3) at row r

        {   // g-pair 0 (g0, g1)
            float4 a0 = *(const float4*)(smb + P0);
            float4 b0 = *(const float4*)(smb + Q0);
            float4 a1 = *(const float4*)(smb + P1);
            float4 b1 = *(const float4*)(smb + Q1);
            v0.x = fmaf(cfA.x, a0.x * b0.x, cfA.y * (a0.x + b0.x));
            v1.x = fmaf(cfA.x, a0.y * b0.y, cfA.y * (a0.y + b0.y));
            v2.x = fmaf(cfA.x, a0.z * b0.z, cfA.y * (a0.z + b0.z));
            v3.x = fmaf(cfA.x, a0.w * b0.w, cfA.y * (a0.w + b0.w));
            v0.y = fmaf(cfA.z, a1.x * b1.x, cfA.w * (a1.x + b1.x));
            v1.y = fmaf(cfA.z, a1.y * b1.y, cfA.w * (a1.y + b1.y));
            v2.y = fmaf(cfA.z, a1.z * b1.z, cfA.w * (a1.z + b1.z));
            v3.y = fmaf(cfA.z, a1.w * b1.w, cfA.w * (a1.w + b1.w));
        }
        {   // g-pair 1 (g2, g3)
            float4 a2 = *(const float4*)(smb + P2);
            float4 b2 = *(const float4*)(smb + Q2);
            float4 a3 = *(const float4*)(smb + P3);
            float4 b3 = *(const float4*)(smb + Q3);
            v0.z = fmaf(cfB.x, a2.x * b2.x, cfB.y * (a2.x + b2.x));
            v1.z = fmaf(cfB.x, a2.y * b2.y, cfB.y * (a2.y + b2.y));
            v2.z = fmaf(cfB.x, a2.z * b2.z, cfB.y * (a2.z + b2.z));
            v3.z = fmaf(cfB.x, a2.w * b2.w, cfB.y * (a2.w + b2.w));
            v0.w = fmaf(cfB.z, a3.x * b3.x, cfB.w * (a3.x + b3.x));
            v1.w = fmaf(cfB.z, a3.y * b3.y, cfB.w * (a3.y + b3.y));
            v2.w = fmaf(cfB.z, a3.z * b3.z, cfB.w * (a3.z + b3.z));
            v3.w = fmaf(cfB.z, a3.w * b3.w, cfB.w * (a3.w + b3.w));
        }

        // Drain previous sweep's bulk copies before overwriting staging.
        if (s > 0) {
            if (tid == 0)
                asm volatile("cp.async.bulk.wait_group 0;" ::: "memory");
        }
        __syncthreads();

        // Dense STS.128 into staging (warp writes one 512-B row chunk).
        char* stg = smb + STAGE_OFF + tid * 16;
        *(float4*)(stg + 0 * STAGE_ROW_B) = v0;
        *(float4*)(stg + 1 * STAGE_ROW_B) = v1;
        *(float4*)(stg + 2 * STAGE_ROW_B) = v2;
        *(float4*)(stg + 3 * STAGE_ROW_B) = v3;
        __syncthreads();

        if (tid == 0) {
            asm volatile("fence.proxy.async.shared::cta;" ::: "memory");
            uint32_t sa = smem_u32 + STAGE_OFF;
            #pragma unroll
            for (int r = 0; r < ROWS; r++) {
                const float* gp = yrow0 + (size_t)r * G + gb;
                asm volatile(
                    "cp.async.bulk.global.shared::cta.bulk_group [%0], [%1], %2;"
                    :: "l"(gp), "r"(sa + r * STAGE_ROW_B), "n"(STAGE_ROW_B)
                    : "memory");
            }
            asm volatile("cp.async.bulk.commit_group;" ::: "memory");
        }
    }

    // Ensure the last bulk group is fully issued/retired before exit.
    if (tid == 0)
        asm volatile("cp.async.bulk.wait_group 0;" ::: "memory");
}

// ---------------------------------------------------------------------------
extern "C" void kernel_launch(void* const* d_in, const int* in_sizes, int n_in,
                              void* d_out, int out_size) {
    const float*        x     = (const float*)d_in[0];
    const unsigned int* il    = (const unsigned int*)d_in[1];
    const unsigned int* ir    = (const unsigned int*)d_in[2];
    const float*        alpha = (const float*)d_in[3];
    float*              y     = (float*)d_out;

    const int G = in_sizes[1];               // 16384
    const int B = in_sizes[0] / MDIM;        // 4096

    prep_kernel<<<(G + 255) / 256, 256>>>(il, ir, alpha, G);

    cudaFuncSetAttribute(gate_kernel, cudaFuncAttributeMaxDynamicSharedMemorySize,
                         SMEM_TOTAL);

    dim3 grid(B / ROWS, 2);                  // (1024, 2), gPerBlock = G/2
    gate_kernel<<<grid, 512, SMEM_TOTAL>>>(x, y, G, G / 2);
}

// round 10
// speedup vs baseline: 1.0851x; 1.0851x over previous
#include <cuda_runtime.h>
#include <stdint.h>

// GateLayer: x (4096,4096) f32, idx_l/idx_r (16384,) int, alpha (16384,3) f32,
// y (4096,16384) f32.
#define MDIM    4096
#define GMAX    16384
#define ROWS    4          // rows per tile (one 16-B quad per column)

// Static device scratch (no cudaMalloc allowed)
__device__ __align__(16) int    g_il[GMAX];   // after sched: swizzled byte offset
__device__ __align__(16) int    g_ir[GMAX];   // after sched: swizzled byte offset
__device__ __align__(16) float2 g_cf[GMAX];

// ---------------------------------------------------------------------------
// Prep with fused int64/int32 detection. Every block samples the first 512
// 32-bit words of il/ir: OR of odd words is 0 iff idx is int64 (values < 4096
// -> high halves zero). Stores RAW column indices + folded softmax coeffs:
//   y = c_ab*ab + c_s*(a+b),  c_ab = w0-w1-2w2, c_s = w1+w2.
// ---------------------------------------------------------------------------
__global__ void prep_kernel(const unsigned int* __restrict__ il_raw,
                            const unsigned int* __restrict__ ir_raw,
                            const float* __restrict__ alpha, int G) {
    int t = threadIdx.x;
    unsigned int acc = 0;
    int i = t * 2 + 1;
    if (i < min(G, 512)) acc = il_raw[i] | ir_raw[i];
    int is64 = !__syncthreads_or(acc != 0u);

    int g = blockIdx.x * blockDim.x + t;
    if (g >= G) return;
    int il, ir;
    if (is64) { il = (int)il_raw[2 * g]; ir = (int)ir_raw[2 * g]; }
    else      { il = (int)il_raw[g];     ir = (int)ir_raw[g];     }
    g_il[g] = il;
    g_ir[g] = ir;

    float a0 = alpha[3 * g + 0], a1 = alpha[3 * g + 1], a2 = alpha[3 * g + 2];
    float m  = fmaxf(a0, fmaxf(a1, a2));
    float e0 = expf(a0 - m), e1 = expf(a1 - m), e2 = expf(a2 - m);
    float inv = 1.0f / (e0 + e1 + e2);
    float w0 = e0 * inv, w1 = e1 * inv, w2 = e2 * inv;
    g_cf[g] = make_float2(w0 - w1 - 2.0f * w2, w1 + w2);
}

// ---------------------------------------------------------------------------
// Conflict scheduler. In the gate kernel, LDS.128 instruction (window, k, op)
// gathers quads for columns {op[g] : g = win*128 + k + 4t, t=0..31}. Its cost
// is the max over the 8 quad-slots (slot(c) = (c&7) ^ ((c>>3)&7)) of the
// column count. The gate is symmetric in (a,b), so swapping il/ir per g moves
// a column between the k-set's 'a' and 'b' instructions -- 2-choice balancing
// flattens both histograms. One thread owns one (window, k) set of 32 g's
// (disjoint, in-place rewrite is safe). Output: PRE-SWIZZLED byte offsets.
// ---------------------------------------------------------------------------
__global__ void sched_kernel(int G) {
    int set = blockIdx.x * blockDim.x + threadIdx.x;
    int nsets = G >> 5;                 // (G/128 windows) * 4 k-sets
    if (set >= nsets) return;
    int win = set >> 2, k = set & 3;
    int base = win * 128 + k;

    unsigned long long hA = 0ull, hB = 0ull;   // 8 byte-counters each
    #pragma unroll 1
    for (int t = 0; t < 32; t++) {
        int g  = base + t * 4;
        int ca = g_il[g], cb = g_ir[g];
        int sa = (ca ^ (ca >> 3)) & 7;
        int sb = (cb ^ (cb >> 3)) & 7;
        int aA = (int)((hA >> (sa * 8)) & 255), bB = (int)((hB >> (sb * 8)) & 255);
        int aB = (int)((hA >> (sb * 8)) & 255), bA = (int)((hB >> (sa * 8)) & 255);
        int costN = max(aA, bB);
        int costS = max(aB, bA);
        int ia = ca, ib = cb;
        if (costS < costN) { ia = cb; ib = ca; int ts = sa; sa = sb; sb = ts; }
        hA += 1ull << (sa * 8);
        hB += 1ull << (sb * 8);
        g_il[g] = (ia ^ ((ia >> 3) & 7)) << 4;   // swizzled quad byte offset
        g_ir[g] = (ib ^ ((ib >> 3) & 7)) << 4;
    }
}

// ---------------------------------------------------------------------------
// Main kernel, 2 blocks/SM (staging of one block overlaps gather of the
// other). SMEM holds 4 rows of x TRANSPOSED: column c is ONE 16-B quad at
// byte P(c) = (c ^ ((c>>3)&7)) << 4 (bijective; staging STS conflict-free).
// One LDS.128 gathers rows 0-3 of one column. Thread = 4 g x 4 rows = 16
// outputs/iter: 8 LDS.128 + 4 STG.128(streaming) + 4 LDG.128.
// ---------------------------------------------------------------------------
__global__ __launch_bounds__(512, 2)
void gate_kernel(const float* __restrict__ x, float* __restrict__ y,
                 int G, int gPerBlock) {
    extern __shared__ float sm[];
    char* smb = (char*)sm;
    const int tid  = threadIdx.x;
    const int warp = tid >> 5, lane = tid & 31;
    const int row0   = blockIdx.x * ROWS;
    const int gstart = blockIdx.y * gPerBlock;

    // ---- Stage: 4 rows, transposed + swizzled, conflict-free STS ----
    {
        const int r  = lane >> 3;              // 0..3
        const int cs = lane & 7;               // 0..7
        const float4* x4 = (const float4*)(x + (size_t)(row0 + r) * MDIM);
        #pragma unroll
        for (int i = 0; i < 8; i++) {
            int c4 = warp * 8 + cs + i * 128;  // float4 index 0..1023
            float4 v = x4[c4];
            int c0 = c4 * 4;
            #pragma unroll
            for (int j = 0; j < 4; j++) {
                int c = c0 + j;
                int P = ((c ^ ((c >> 3) & 7)) << 4) + r * 4;
                *(float*)(smb + P) = (&v.x)[j];
            }
        }
    }
    __syncthreads();

    float* yrow0 = y + (size_t)row0 * G;

    // 4 g per thread; 512 threads cover 2048 g per sweep.
    #pragma unroll 2
    for (int gb = gstart + tid * 4; gb < gstart + gPerBlock; gb += 2048) {
        int4   P   = *(const int4*)&g_il[gb];         // pre-swizzled offsets
        int4   Q   = *(const int4*)&g_ir[gb];
        float4 cfA = *(const float4*)&g_cf[gb];       // (cab0,cs0,cab1,cs1)
        float4 cfB = *(const float4*)&g_cf[gb + 2];   // (cab2,cs2,cab3,cs3)

        float4 v0, v1, v2, v3;   // v{r} = outputs (g0,g1,g2,g3) at row r

        {   // g-pair 0 (g0, g1)
            float4 a0 = *(const float4*)(smb + P.x);
            float4 b0 = *(const float4*)(smb + Q.x);
            float4 a1 = *(const float4*)(smb + P.y);
            float4 b1 = *(const float4*)(smb + Q.y);
            v0.x = fmaf(cfA.x, a0.x * b0.x, cfA.y * (a0.x + b0.x));
            v1.x = fmaf(cfA.x, a0.y * b0.y, cfA.y * (a0.y + b0.y));
            v2.x = fmaf(cfA.x, a0.z * b0.z, cfA.y * (a0.z + b0.z));
            v3.x = fmaf(cfA.x, a0.w * b0.w, cfA.y * (a0.w + b0.w));
            v0.y = fmaf(cfA.z, a1.x * b1.x, cfA.w * (a1.x + b1.x));
            v1.y = fmaf(cfA.z, a1.y * b1.y, cfA.w * (a1.y + b1.y));
            v2.y = fmaf(cfA.z, a1.z * b1.z, cfA.w * (a1.z + b1.z));
            v3.y = fmaf(cfA.z, a1.w * b1.w, cfA.w * (a1.w + b1.w));
        }
        {   // g-pair 1 (g2, g3)
            float4 a2 = *(const float4*)(smb + P.z);
            float4 b2 = *(const float4*)(smb + Q.z);
            float4 a3 = *(const float4*)(smb + P.w);
            float4 b3 = *(const float4*)(smb + Q.w);
            v0.z = fmaf(cfB.x, a2.x * b2.x, cfB.y * (a2.x + b2.x));
            v1.z = fmaf(cfB.x, a2.y * b2.y, cfB.y * (a2.y + b2.y));
            v2.z = fmaf(cfB.x, a2.z * b2.z, cfB.y * (a2.z + b2.z));
            v3.z = fmaf(cfB.x, a2.w * b2.w, cfB.y * (a2.w + b2.w));
            v0.w = fmaf(cfB.z, a3.x * b3.x, cfB.w * (a3.x + b3.x));
            v1.w = fmaf(cfB.z, a3.y * b3.y, cfB.w * (a3.y + b3.y));
            v2.w = fmaf(cfB.z, a3.z * b3.z, cfB.w * (a3.z + b3.z));
            v3.w = fmaf(cfB.z, a3.w * b3.w, cfB.w * (a3.w + b3.w));
        }

        // 4 coalesced streaming STG.128 (y is never re-read; keep x in L2)
        float* yp = yrow0 + gb;
        __stcs((float4*)(yp + 0 * (size_t)G), v0);
        __stcs((float4*)(yp + 1 * (size_t)G), v1);
        __stcs((float4*)(yp + 2 * (size_t)G), v2);
        __stcs((float4*)(yp + 3 * (size_t)G), v3);
    }
}

// ---------------------------------------------------------------------------
extern "C" void kernel_launch(void* const* d_in, const int* in_sizes, int n_in,
                              void* d_out, int out_size) {
    const float*        x     = (const float*)d_in[0];
    const unsigned int* il    = (const unsigned int*)d_in[1];
    const unsigned int* ir    = (const unsigned int*)d_in[2];
    const float*        alpha = (const float*)d_in[3];
    float*              y     = (float*)d_out;

    const int G = in_sizes[1];               // 16384
    const int B = in_sizes[0] / MDIM;        // 4096

    prep_kernel<<<(G + 255) / 256, 256>>>(il, ir, alpha, G);
    sched_kernel<<<(G / 32 + 255) / 256, 256>>>(G);

    const int smemBytes = MDIM * 16;         // 65536 B (one quad per column)
    cudaFuncSetAttribute(gate_kernel, cudaFuncAttributeMaxDynamicSharedMemorySize,
                         smemBytes);

    dim3 grid(B / ROWS, 2);                  // (1024, 2), gPerBlock = G/2
    gate_kernel<<<grid, 512, smemBytes>>>(x, y, G, G / 2);
}